// round 9
// baseline (speedup 1.0000x reference)
#include <cuda_runtime.h>
#include <cuda_fp16.h>

// out[v,:] = coef * ( 2*x[v,:]*S1 + S2 ), S1 = sum_k x[nbr[v,k]], S2 = sum_k x[nbr[v,k]]^2
// N=100000, K=16, D=128, coef = (2/6)/16 = 1/48.
// fp16 gather route, 1 node/warp.
//  - idx via 4x int4; 16 independent LDG.64 gathers of 256B fp16 rows
//  - half2 accumulation in runs of 8, fp32 flush (2 flushes)
//  - self row from fp16 scratch; out stored streaming (evict-first)
//  - convert reads x with DEFAULT caching: x(51MB)+xh(25.6MB)=77MB fits L2,
//    so on graph replays the convert pass runs at L2 bandwidth, not DRAM.

#define TMP_N 100000
#define TMP_D 128
#define TMP_K 16

// fp16 copy of x: [N, 32] uint2 (4 halves per lane).
__device__ __align__(16) uint2 g_xh[TMP_N * TMP_D / 4];

__global__ __launch_bounds__(256) void TMP_convert_kernel(
    const float4* __restrict__ x, int n4)
{
    int i = blockIdx.x * blockDim.x + threadIdx.x;
    if (i >= n4) return;
    float4 v = __ldg(&x[i]);   // default caching: keep x L2-resident across replays
    __half2 h0 = __floats2half2_rn(v.x, v.y);
    __half2 h1 = __floats2half2_rn(v.z, v.w);
    uint2 p;
    p.x = *reinterpret_cast<unsigned int*>(&h0);
    p.y = *reinterpret_cast<unsigned int*>(&h1);
    g_xh[i] = p;
}

static __device__ __forceinline__ __half2 h2bits(unsigned int u) {
    return *reinterpret_cast<__half2*>(&u);
}

__global__ __launch_bounds__(256) void TMessagePassing_11974368821731_kernel(
    const int4* __restrict__ nbr4,   // [N, 4] int4 (= [N,16] int)
    float4*     __restrict__ out,    // [N, 32] float4
    int n)
{
    int warp = (int)((blockIdx.x * blockDim.x + threadIdx.x) >> 5);
    int lane = threadIdx.x & 31;
    if (warp >= n) return;

    const float coef = 1.0f / 48.0f;
    const uint2* __restrict__ xh = g_xh;

    // 16 neighbor indices via 4 vector loads (uniform -> broadcast).
    const int4* nv = nbr4 + (long long)warp * 4;
    int idx[TMP_K];
#pragma unroll
    for (int r = 0; r < 4; r++) {
        int4 q = __ldg(&nv[r]);
        idx[4 * r + 0] = q.x; idx[4 * r + 1] = q.y;
        idx[4 * r + 2] = q.z; idx[4 * r + 3] = q.w;
    }

    // Self row (fp16, L2-resident), issued early.
    uint2 ps = __ldg(&xh[(unsigned)warp * 32u + (unsigned)lane]);

    float4 s1 = make_float4(0.f, 0.f, 0.f, 0.f);
    float4 s2 = make_float4(0.f, 0.f, 0.f, 0.f);

    // 2 runs of 8 gathers; half2 accumulation within a run, fp32 flush after.
#pragma unroll
    for (int run = 0; run < 2; run++) {
        __half2 t0, t1, q0, q1;
        {
            uint2 p = __ldg(&xh[(unsigned)idx[8 * run] * 32u + (unsigned)lane]);
            __half2 a0 = h2bits(p.x), a1 = h2bits(p.y);
            t0 = a0;              t1 = a1;
            q0 = __hmul2(a0, a0); q1 = __hmul2(a1, a1);
        }
#pragma unroll
        for (int j = 1; j < 8; j++) {
            uint2 p = __ldg(&xh[(unsigned)idx[8 * run + j] * 32u + (unsigned)lane]);
            __half2 a0 = h2bits(p.x), a1 = h2bits(p.y);
            t0 = __hadd2(t0, a0);     t1 = __hadd2(t1, a1);
            q0 = __hfma2(a0, a0, q0); q1 = __hfma2(a1, a1, q1);
        }
        float2 f;
        f = __half22float2(t0); s1.x += f.x; s1.y += f.y;
        f = __half22float2(t1); s1.z += f.x; s1.w += f.y;
        f = __half22float2(q0); s2.x += f.x; s2.y += f.y;
        f = __half22float2(q1); s2.z += f.x; s2.w += f.y;
    }

    float2 xv0 = __half22float2(h2bits(ps.x));
    float2 xv1 = __half22float2(h2bits(ps.y));

    float4 o;
    o.x = coef * fmaf(xv0.x + xv0.x, s1.x, s2.x);
    o.y = coef * fmaf(xv0.y + xv0.y, s1.y, s2.y);
    o.z = coef * fmaf(xv1.x + xv1.x, s1.z, s2.z);
    o.w = coef * fmaf(xv1.y + xv1.y, s1.w, s2.w);

    // Streaming store: keep out from evicting x/xh in L2.
    __stcs(&out[(long long)warp * 32 + lane], o);
}

extern "C" void kernel_launch(void* const* d_in, const int* in_sizes, int n_in,
                              void* d_out, int out_size)
{
    const float4* x    = (const float4*)d_in[0];
    const int4*   nbr4 = (const int4*)d_in[1];
    float4*       out  = (float4*)d_out;

    int n  = in_sizes[1] / TMP_K;      // N nodes
    int n4 = in_sizes[0] / 4;          // N*D/4 float4s

    TMP_convert_kernel<<<(n4 + 255) / 256, 256>>>(x, n4);

    int warps_per_block = 256 / 32;    // 8 nodes per block
    int blocks = (n + warps_per_block - 1) / warps_per_block;
    TMessagePassing_11974368821731_kernel<<<blocks, 256>>>(nbr4, out, n);
}

// round 10
// speedup vs baseline: 1.4790x; 1.4790x over previous
#include <cuda_runtime.h>
#include <cuda_fp16.h>

// out[v,:] = coef * ( 2*x[v,:]*S1 + S2 ), S1 = sum_k x[nbr[v,k]], S2 = sum_k x[nbr[v,k]]^2
// N=100000, K=16, D=128, coef = (2/6)/16 = 1/48.
// fp16 gather route, 1 node/warp. R8 config (convert uses __ldcs so x never
// pollutes L2 and the 25.6MB xh scratch stays resident) + one change:
// ALL 16 gather loads are issued into a register array before accumulation,
// forcing MLP=16 per warp (R8's 32-reg build could only keep ~6-8 in flight).

#define TMP_N 100000
#define TMP_D 128
#define TMP_K 16

// fp16 copy of x: [N, 32] uint2 (4 halves per lane).
__device__ __align__(16) uint2 g_xh[TMP_N * TMP_D / 4];

__global__ __launch_bounds__(256) void TMP_convert_kernel(
    const float4* __restrict__ x, int n4)
{
    int i = blockIdx.x * blockDim.x + threadIdx.x;
    if (i >= n4) return;
    float4 v = __ldcs(&x[i]);   // evict-first: keep x OUT of L2 (protect xh)
    __half2 h0 = __floats2half2_rn(v.x, v.y);
    __half2 h1 = __floats2half2_rn(v.z, v.w);
    uint2 p;
    p.x = *reinterpret_cast<unsigned int*>(&h0);
    p.y = *reinterpret_cast<unsigned int*>(&h1);
    g_xh[i] = p;
}

static __device__ __forceinline__ __half2 h2bits(unsigned int u) {
    return *reinterpret_cast<__half2*>(&u);
}

__global__ __launch_bounds__(256) void TMessagePassing_11974368821731_kernel(
    const int4* __restrict__ nbr4,   // [N, 4] int4 (= [N,16] int)
    float4*     __restrict__ out,    // [N, 32] float4
    int n)
{
    int warp = (int)((blockIdx.x * blockDim.x + threadIdx.x) >> 5);
    int lane = threadIdx.x & 31;
    if (warp >= n) return;

    const float coef = 1.0f / 48.0f;
    const uint2* __restrict__ xh = g_xh;

    // 16 neighbor indices via 4 vector loads (uniform -> broadcast).
    const int4* nv = nbr4 + (long long)warp * 4;
    int idx[TMP_K];
#pragma unroll
    for (int r = 0; r < 4; r++) {
        int4 q = __ldg(&nv[r]);
        idx[4 * r + 0] = q.x; idx[4 * r + 1] = q.y;
        idx[4 * r + 2] = q.z; idx[4 * r + 3] = q.w;
    }

    // Self row (fp16, L2-resident).
    uint2 ps = __ldg(&xh[(unsigned)warp * 32u + (unsigned)lane]);

    // Issue ALL 16 gathers up front -> MLP=16 per warp.
    uint2 p[TMP_K];
#pragma unroll
    for (int k = 0; k < TMP_K; k++)
        p[k] = __ldg(&xh[(unsigned)idx[k] * 32u + (unsigned)lane]);

    float4 s1 = make_float4(0.f, 0.f, 0.f, 0.f);
    float4 s2 = make_float4(0.f, 0.f, 0.f, 0.f);

    // 2 runs of 8; half2 accumulation within a run, fp32 flush after.
#pragma unroll
    for (int run = 0; run < 2; run++) {
        __half2 t0, t1, q0, q1;
        {
            __half2 a0 = h2bits(p[8 * run].x), a1 = h2bits(p[8 * run].y);
            t0 = a0;              t1 = a1;
            q0 = __hmul2(a0, a0); q1 = __hmul2(a1, a1);
        }
#pragma unroll
        for (int j = 1; j < 8; j++) {
            __half2 a0 = h2bits(p[8 * run + j].x), a1 = h2bits(p[8 * run + j].y);
            t0 = __hadd2(t0, a0);     t1 = __hadd2(t1, a1);
            q0 = __hfma2(a0, a0, q0); q1 = __hfma2(a1, a1, q1);
        }
        float2 f;
        f = __half22float2(t0); s1.x += f.x; s1.y += f.y;
        f = __half22float2(t1); s1.z += f.x; s1.w += f.y;
        f = __half22float2(q0); s2.x += f.x; s2.y += f.y;
        f = __half22float2(q1); s2.z += f.x; s2.w += f.y;
    }

    float2 xv0 = __half22float2(h2bits(ps.x));
    float2 xv1 = __half22float2(h2bits(ps.y));

    float4 o;
    o.x = coef * fmaf(xv0.x + xv0.x, s1.x, s2.x);
    o.y = coef * fmaf(xv0.y + xv0.y, s1.y, s2.y);
    o.z = coef * fmaf(xv1.x + xv1.x, s1.z, s2.z);
    o.w = coef * fmaf(xv1.y + xv1.y, s1.w, s2.w);

    // Streaming store: keep out from evicting xh in L2.
    __stcs(&out[(long long)warp * 32 + lane], o);
}

extern "C" void kernel_launch(void* const* d_in, const int* in_sizes, int n_in,
                              void* d_out, int out_size)
{
    const float4* x    = (const float4*)d_in[0];
    const int4*   nbr4 = (const int4*)d_in[1];
    float4*       out  = (float4*)d_out;

    int n  = in_sizes[1] / TMP_K;      // N nodes
    int n4 = in_sizes[0] / 4;          // N*D/4 float4s

    TMP_convert_kernel<<<(n4 + 255) / 256, 256>>>(x, n4);

    int warps_per_block = 256 / 32;    // 8 nodes per block
    int blocks = (n + warps_per_block - 1) / warps_per_block;
    TMessagePassing_11974368821731_kernel<<<blocks, 256>>>(nbr4, out, n);
}